// round 5
// baseline (speedup 1.0000x reference)
#include <cuda_runtime.h>
#include <cstdint>
#include <cstddef>

// LSTM_LSTM_455266533595 : 2-layer LSTM encoder (B=256,T=336,H=1024) +
// 96-step 2-layer decoder with FC feedback.
// SINGLE persistent kernel (one graph node — avoids the 2MB graph-upload
// residue that failed R1). 128 co-resident CTAs, software grid barrier
// between recurrence phases. fp32 SIMT GEMM with packed fma.rn.f32x2.

#define Bsz    256
#define Hdim   1024
#define Tlen   336
#define OUTLEN 96
#define BT     64      // batch tile per CTA
#define NT     32      // hidden units per CTA (x4 gates = 128 gate cols)
#define GT     128     // gate columns per CTA
#define KC     32      // K chunk
#define KCP    34      // padded K chunk (conflict-free f32x2 reads)
#define BH     (Bsz*Hdim)
#define NCTA   128     // (4 batch tiles) x (32 hidden tiles) — all co-resident

// ---------------- persistent device state (no allocations allowed) ----------
__device__ float g_h0[2][BH];
__device__ float g_h1[2][BH];
__device__ float g_c0[BH];
__device__ float g_c1[BH];
__device__ float g_xt[Bsz];
__device__ unsigned g_cnt;   // zero-initialized; each barrier leaves it at 0
__device__ unsigned g_gen;   // monotonically increasing generation counter

__device__ __forceinline__ float sigmoidf_(float x) { return 1.0f / (1.0f + expf(-x)); }

// ---------------------------------------------------------------------------
// Grid-wide barrier: sense via generation counter. All 128 CTAs are resident
// (grid < #SMs), so spinning is deadlock-free. Leader resets the count BEFORE
// releasing the generation bump, so early re-arrivals at the next barrier
// cannot race the reset.
// ---------------------------------------------------------------------------
__device__ __forceinline__ void grid_sync() {
    __syncthreads();
    if (threadIdx.x == 0) {
        __threadfence();                                   // release prior writes
        unsigned g = *(volatile unsigned*)&g_gen;          // read BEFORE arriving
        unsigned a = atomicAdd(&g_cnt, 1u);
        if (a == NCTA - 1) {
            atomicExch(&g_cnt, 0u);
            __threadfence();
            atomicAdd(&g_gen, 1u);
        } else {
            while (*(volatile unsigned*)&g_gen == g) { __nanosleep(64); }
        }
        __threadfence();                                   // acquire
    }
    __syncthreads();
}

// ---------------------------------------------------------------------------
// One LSTM cell phase for this CTA's (64 batch x 32 hidden) tile.
//   gates = [A1 @ W1^T] + [A2 @ W2^T] + bias + xs[b]*wih   (A1/xs optional)
// Thread (tx=tid&15, ty=tid>>4) owns a 4(m) x 8(gate-col) register tile;
// gate-col(j) = 16*j + tx  ->  gate = j>>1, hidden = (j&1)*16 + tx, so the
// full i/f/g/o set for each (m, hidden) lives in one thread's registers.
// ---------------------------------------------------------------------------
__device__ __noinline__ void lstm_phase(
    const float* __restrict__ A1, const float* __restrict__ W1,
    const float* __restrict__ A2, const float* __restrict__ W2,
    const float* __restrict__ bias,
    const float* __restrict__ xs, int xs_stride,
    const float* __restrict__ wih,
    float* c, float* __restrict__ h_out)
{
    __shared__ float As[BT][KCP];
    __shared__ float Bs[GT][KCP];

    const int tid = threadIdx.x;
    const int tx = tid & 15;
    const int ty = tid >> 4;
    const int m0 = (blockIdx.x & 3) * BT;
    const int n0 = (blockIdx.x >> 2) * NT;

    unsigned long long acc[4][8];   // f32x2 accumulators (.x even-k, .y odd-k)
#pragma unroll
    for (int i = 0; i < 4; i++)
#pragma unroll
        for (int j = 0; j < 8; j++) acc[i][j] = 0ull;

    const float* Ap[2] = { A1, A2 };
    const float* Wp[2] = { W1, W2 };

#pragma unroll 1
    for (int pass = 0; pass < 2; pass++) {
        const float* A = Ap[pass];
        if (A == nullptr) continue;
        const float* W = Wp[pass];

#pragma unroll 1
        for (int k0 = 0; k0 < Hdim; k0 += KC) {
            __syncthreads();
            // A tile: 64 rows x 32 k (512 float4, 2/thread)
#pragma unroll
            for (int j = 0; j < 2; j++) {
                int lin = tid + j * 256;
                int row = lin >> 3;
                int kq  = lin & 7;
                float4 v = *reinterpret_cast<const float4*>(
                    A + (size_t)(m0 + row) * Hdim + k0 + kq * 4);
                float2* d = reinterpret_cast<float2*>(&As[row][kq * 4]);
                d[0] = make_float2(v.x, v.y);
                d[1] = make_float2(v.z, v.w);
            }
            // W tile: 128 gate-cols x 32 k (1024 float4, 4/thread)
#pragma unroll
            for (int j = 0; j < 4; j++) {
                int lin = tid + j * 256;
                int cc2 = lin >> 3;
                int kq  = lin & 7;
                int gi  = ((cc2 >> 5) << 10) + n0 + (cc2 & 31);  // gate*1024 + n
                float4 v = *reinterpret_cast<const float4*>(
                    W + (size_t)gi * Hdim + k0 + kq * 4);
                float2* d = reinterpret_cast<float2*>(&Bs[cc2][kq * 4]);
                d[0] = make_float2(v.x, v.y);
                d[1] = make_float2(v.z, v.w);
            }
            __syncthreads();

#pragma unroll
            for (int kk = 0; kk < KC / 2; kk++) {
                unsigned long long a2[4], b2[8];
#pragma unroll
                for (int i = 0; i < 4; i++)
                    a2[i] = *reinterpret_cast<const unsigned long long*>(&As[ty * 4 + i][kk * 2]);
#pragma unroll
                for (int j = 0; j < 8; j++)
                    b2[j] = *reinterpret_cast<const unsigned long long*>(&Bs[j * 16 + tx][kk * 2]);
#pragma unroll
                for (int i = 0; i < 4; i++)
#pragma unroll
                    for (int j = 0; j < 8; j++)
                        asm("fma.rn.f32x2 %0, %1, %2, %0;"
                            : "+l"(acc[i][j]) : "l"(a2[i]), "l"(b2[j]));
            }
        }
    }

    // pointwise LSTM update (full gate set in registers)
    float bI[2], bF[2], bG[2], bO[2], wI[2], wF[2], wG[2], wO[2];
#pragma unroll
    for (int h = 0; h < 2; h++) {
        int n = n0 + h * 16 + tx;
        bI[h] = bias[n];
        bF[h] = bias[Hdim + n];
        bG[h] = bias[2 * Hdim + n];
        bO[h] = bias[3 * Hdim + n];
        if (wih) {
            wI[h] = wih[n];
            wF[h] = wih[Hdim + n];
            wG[h] = wih[2 * Hdim + n];
            wO[h] = wih[3 * Hdim + n];
        } else {
            wI[h] = wF[h] = wG[h] = wO[h] = 0.0f;
        }
    }
#pragma unroll
    for (int i = 0; i < 4; i++) {
        int m = m0 + ty * 4 + i;
        float xv = xs ? xs[(size_t)m * xs_stride] : 0.0f;
#pragma unroll
        for (int h = 0; h < 2; h++) {
            float2 vi = *reinterpret_cast<float2*>(&acc[i][0 + h]);
            float2 vf = *reinterpret_cast<float2*>(&acc[i][2 + h]);
            float2 vg = *reinterpret_cast<float2*>(&acc[i][4 + h]);
            float2 vo = *reinterpret_cast<float2*>(&acc[i][6 + h]);
            float pi = vi.x + vi.y + bI[h] + xv * wI[h];
            float pf = vf.x + vf.y + bF[h] + xv * wF[h];
            float pg = vg.x + vg.y + bG[h] + xv * wG[h];
            float po = vo.x + vo.y + bO[h] + xv * wO[h];
            int idx = m * Hdim + n0 + h * 16 + tx;
            float cc = c[idx];
            float ig = sigmoidf_(pi);
            float fg = sigmoidf_(pf);
            float og = sigmoidf_(po);
            float gg = tanhf(pg);
            float cn = fg * cc + ig * gg;
            float hn = og * tanhf(cn);
            c[idx]     = cn;
            h_out[idx] = hn;
        }
    }
}

// FC head phase: CTAs 0..31, one warp per batch row (8 rows/CTA).
__device__ __forceinline__ void fc_phase(
    const float* __restrict__ h1, const float* __restrict__ fcW,
    const float* __restrict__ fcb, float* __restrict__ out,
    float* __restrict__ xt, int s)
{
    if (blockIdx.x >= 32) return;
    int warp = threadIdx.x >> 5;
    int lane = threadIdx.x & 31;
    int b = blockIdx.x * 8 + warp;
    float sum = 0.0f;
    const float* hr = h1 + (size_t)b * Hdim;
#pragma unroll 8
    for (int k = lane; k < Hdim; k += 32) sum += hr[k] * fcW[k];
#pragma unroll
    for (int off = 16; off > 0; off >>= 1)
        sum += __shfl_down_sync(0xFFFFFFFFu, sum, off);
    if (lane == 0) {
        float y = sum + fcb[0];
        out[(size_t)b * OUTLEN + s] = y;
        xt[b] = y;
    }
}

// ---------------------------------------------------------------------------
__global__ void __launch_bounds__(256) lstm_persistent_kernel(
    const float* __restrict__ x,
    const float* __restrict__ enc_Wih0, const float* __restrict__ enc_Whh0,
    const float* __restrict__ enc_b0,
    const float* __restrict__ enc_Wih1, const float* __restrict__ enc_Whh1,
    const float* __restrict__ enc_b1,
    const float* __restrict__ dec_Wih0, const float* __restrict__ dec_Whh0,
    const float* __restrict__ dec_b0,
    const float* __restrict__ dec_Wih1, const float* __restrict__ dec_Whh1,
    const float* __restrict__ dec_b1,
    const float* __restrict__ fc_W, const float* __restrict__ fc_b,
    float* __restrict__ out)
{
    float* h0 = &g_h0[0][0];
    float* h1 = &g_h1[0][0];
    float* c0 = g_c0;
    float* c1 = g_c1;
    float* xt = g_xt;

    // ---- init: zero read-side ping buffers + cell states; seed feedback ----
    {
        const int per = BH / NCTA;              // 2048 floats per CTA
        float4 z = make_float4(0.f, 0.f, 0.f, 0.f);
        int base = blockIdx.x * per;
#pragma unroll
        for (int j = 0; j < per / (256 * 4); j++) {      // 2 float4 per thread
            int i = base + (threadIdx.x + j * 256) * 4;
            *reinterpret_cast<float4*>(&g_h0[0][i]) = z;
            *reinterpret_cast<float4*>(&g_h1[0][i]) = z;
            *reinterpret_cast<float4*>(&g_c0[i]) = z;
            *reinterpret_cast<float4*>(&g_c1[i]) = z;
        }
        if (blockIdx.x == 0)
            xt[threadIdx.x] = x[(size_t)threadIdx.x * Tlen + (Tlen - 1)];
    }
    grid_sync();

    int p0 = 0, p1 = 0;

    // -------- encoder --------
#pragma unroll 1
    for (int t = 0; t < Tlen; t++) {
        lstm_phase(nullptr, nullptr,
                   h0 + (size_t)p0 * BH, enc_Whh0, enc_b0,
                   x + t, Tlen, enc_Wih0,
                   c0, h0 + (size_t)(p0 ^ 1) * BH);
        p0 ^= 1;
        grid_sync();
        lstm_phase(h0 + (size_t)p0 * BH, enc_Wih1,
                   h1 + (size_t)p1 * BH, enc_Whh1, enc_b1,
                   nullptr, 0, nullptr,
                   c1, h1 + (size_t)(p1 ^ 1) * BH);
        p1 ^= 1;
        grid_sync();
    }

    // -------- decoder (96 autoregressive steps) --------
#pragma unroll 1
    for (int s = 0; s < OUTLEN; s++) {
        lstm_phase(nullptr, nullptr,
                   h0 + (size_t)p0 * BH, dec_Whh0, dec_b0,
                   xt, 1, dec_Wih0,
                   c0, h0 + (size_t)(p0 ^ 1) * BH);
        p0 ^= 1;
        grid_sync();
        lstm_phase(h0 + (size_t)p0 * BH, dec_Wih1,
                   h1 + (size_t)p1 * BH, dec_Whh1, dec_b1,
                   nullptr, 0, nullptr,
                   c1, h1 + (size_t)(p1 ^ 1) * BH);
        p1 ^= 1;
        grid_sync();
        fc_phase(h1 + (size_t)p1 * BH, fc_W, fc_b, out, xt, s);
        grid_sync();
    }
}

// ---------------------------------------------------------------------------
extern "C" void kernel_launch(void* const* d_in, const int* in_sizes, int n_in,
                              void* d_out, int out_size)
{
    (void)in_sizes; (void)n_in; (void)out_size;
    lstm_persistent_kernel<<<NCTA, 256>>>(
        (const float*)d_in[0],
        (const float*)d_in[1],  (const float*)d_in[2],  (const float*)d_in[3],
        (const float*)d_in[4],  (const float*)d_in[5],  (const float*)d_in[6],
        (const float*)d_in[7],  (const float*)d_in[8],  (const float*)d_in[9],
        (const float*)d_in[10], (const float*)d_in[11], (const float*)d_in[12],
        (const float*)d_in[13], (const float*)d_in[14],
        (float*)d_out);
}

// round 7
// speedup vs baseline: 3.1308x; 3.1308x over previous
#include <cuda_runtime.h>
#include <cuda_bf16.h>
#include <cstdint>
#include <cstddef>

// Persistent split-bf16 HMMA LSTM (portable PTX: mma.sync + ldmatrix).
// 128 CTAs = 2 M-tiles(128 rows) x 64 N-tiles(16 hidden x 4 gates = 64 cols).
#define Bsz 256
#define Hdim 1024
#define Tlen 336
#define OUTLEN 96
#define BH (Bsz*Hdim)
#define NCTA 128
#define KCH 64                    // k per chunk
#define ASTR 144                  // padded smem row stride (bytes) for 128B rows
#define STG 55296                 // stage bytes: Ahi 18432 | Alo 18432 | Bhi 9216 | Blo 9216
#define OFF_ALO 18432
#define OFF_BHI 36864
#define OFF_BLO 46080
#define SMEM_TOTAL (3*STG)

// ---------------- persistent device state ----------------
__device__ __align__(16) __nv_bfloat16 g_Wh[6][4096 * 1024];   // gate-permuted [n_t*64+col][k]
__device__ __align__(16) __nv_bfloat16 g_Wl[6][4096 * 1024];
__device__ __align__(16) __nv_bfloat16 g_Ah[2][2][BH];          // h state hi [layer][ping][m][k]
__device__ __align__(16) __nv_bfloat16 g_Al[2][2][BH];          // h state lo
__device__ float g_c0[BH], g_c1[BH], g_h1f[BH], g_xt[Bsz];
__device__ unsigned g_cnt, g_gen;

__device__ __forceinline__ uint32_t smem_u32(const void* p) {
    uint32_t a;
    asm("{ .reg .u64 t; cvta.to.shared.u64 t, %1; cvt.u32.u64 %0, t; }" : "=r"(a) : "l"(p));
    return a;
}
__device__ __forceinline__ void cpa16(uint32_t d, const void* s) {
    asm volatile("cp.async.cg.shared.global [%0], [%1], 16;" :: "r"(d), "l"(s));
}
__device__ __forceinline__ void cp_commit() { asm volatile("cp.async.commit_group;" ::: "memory"); }
template <int N> __device__ __forceinline__ void cp_wait() {
    asm volatile("cp.async.wait_group %0;" :: "n"(N) : "memory");
}
__device__ __forceinline__ void ldm4(uint32_t* r, uint32_t a) {
    asm volatile("ldmatrix.sync.aligned.m8n8.x4.shared.b16 {%0,%1,%2,%3}, [%4];"
        : "=r"(r[0]), "=r"(r[1]), "=r"(r[2]), "=r"(r[3]) : "r"(a));
}
__device__ __forceinline__ void mma16816(float* c, const uint32_t* a, uint32_t b0, uint32_t b1) {
    asm volatile(
        "mma.sync.aligned.m16n8k16.row.col.f32.bf16.bf16.f32 "
        "{%0,%1,%2,%3}, {%4,%5,%6,%7}, {%8,%9}, {%0,%1,%2,%3};"
        : "+f"(c[0]), "+f"(c[1]), "+f"(c[2]), "+f"(c[3])
        : "r"(a[0]), "r"(a[1]), "r"(a[2]), "r"(a[3]), "r"(b0), "r"(b1));
}
__device__ __forceinline__ float sigmoidf_(float x) { return 1.0f / (1.0f + expf(-x)); }

__device__ __forceinline__ void grid_sync() {
    __syncthreads();
    if (threadIdx.x == 0) {
        __threadfence();
        unsigned g = *(volatile unsigned*)&g_gen;
        unsigned a = atomicAdd(&g_cnt, 1u);
        if (a == NCTA - 1) {
            atomicExch(&g_cnt, 0u);
            __threadfence();
            atomicAdd(&g_gen, 1u);
        } else {
            while (*(volatile unsigned*)&g_gen == g) { __nanosleep(64); }
        }
        __threadfence();
    }
    __syncthreads();
}

// Split+permute 6 weight matrices into bf16 hi/lo: dst col = n_t*64 + gate*16 + hid%16.
__device__ void prologue(const float* const* Ws, const float* x) {
    const int gt = blockIdx.x * 256 + threadIdx.x;
#pragma unroll 1
    for (int mat = 0; mat < 6; mat++) {
        const float* src = Ws[mat];
#pragma unroll 1
        for (int p = gt; p < (4096 * 1024 / 2); p += NCTA * 256) {
            int gr = p >> 9;
            int k  = (p & 511) << 1;
            float2 v = *(const float2*)(src + (size_t)gr * 1024 + k);
            int gate = gr >> 10, hid = gr & 1023;
            size_t off = ((size_t)(hid >> 4) * 64 + gate * 16 + (hid & 15)) * 1024 + k;
            __nv_bfloat16 h0 = __float2bfloat16(v.x);
            __nv_bfloat16 h1 = __float2bfloat16(v.y);
            __nv_bfloat16 l0 = __float2bfloat16(v.x - __bfloat162float(h0));
            __nv_bfloat16 l1 = __float2bfloat16(v.y - __bfloat162float(h1));
            *(uint32_t*)&g_Wh[mat][off] = (uint32_t)__bfloat16_as_ushort(h0) | ((uint32_t)__bfloat16_as_ushort(h1) << 16);
            *(uint32_t*)&g_Wl[mat][off] = (uint32_t)__bfloat16_as_ushort(l0) | ((uint32_t)__bfloat16_as_ushort(l1) << 16);
        }
    }
    float4 zf = make_float4(0.f, 0.f, 0.f, 0.f);
    uint4 z4 = make_uint4(0, 0, 0, 0);
    for (int i = gt; i < BH / 4; i += NCTA * 256) {
        ((float4*)g_c0)[i] = zf;
        ((float4*)g_c1)[i] = zf;
    }
    for (int i = gt; i < BH / 8; i += NCTA * 256) {
        ((uint4*)g_Ah[0][0])[i] = z4;
        ((uint4*)g_Al[0][0])[i] = z4;
        ((uint4*)g_Ah[1][0])[i] = z4;
        ((uint4*)g_Al[1][0])[i] = z4;
    }
    if (gt < Bsz) g_xt[gt] = x[(size_t)gt * Tlen + (Tlen - 1)];
}

// One recurrence phase: D(128x64) = sum over passes A@W^T (3-term split-bf16),
// fused LSTM pointwise, state write-back.
__device__ __noinline__ void lstm_phase(
    uint32_t tb, int npass,
    const __nv_bfloat16* A0h, const __nv_bfloat16* A0l,
    const __nv_bfloat16* W0h, const __nv_bfloat16* W0l,
    const __nv_bfloat16* A1h, const __nv_bfloat16* A1l,
    const __nv_bfloat16* W1h, const __nv_bfloat16* W1l,
    const float* __restrict__ bias, const float* __restrict__ wih,
    const float* __restrict__ xs, int xs_stride,
    float* __restrict__ cst,
    __nv_bfloat16* __restrict__ oAh, __nv_bfloat16* __restrict__ oAl,
    float* __restrict__ of32)
{
    const int tid = threadIdx.x;
    const int m_t = blockIdx.x & 1;
    const int n_t = blockIdx.x >> 1;
    const int C = npass << 4;

    const __nv_bfloat16* Ah[2] = { A0h + m_t * 128 * Hdim, A1h ? A1h + m_t * 128 * Hdim : A0h };
    const __nv_bfloat16* Al[2] = { A0l + m_t * 128 * Hdim, A1l ? A1l + m_t * 128 * Hdim : A0l };
    const __nv_bfloat16* Wh[2] = { W0h + (size_t)n_t * 64 * Hdim, W1h ? W1h + (size_t)n_t * 64 * Hdim : W0h };
    const __nv_bfloat16* Wl[2] = { W0l + (size_t)n_t * 64 * Hdim, W1l ? W1l + (size_t)n_t * 64 * Hdim : W0l };

    auto load_chunk = [&](int ch) {
        const int pass = ch >> 4, c = ch & 15;
        const uint32_t st = tb + (ch % 3) * STG;
        const char* ah = (const char*)Ah[pass] + c * 128;   // row stride 2048B
        const char* al = (const char*)Al[pass] + c * 128;
        const char* wh = (const char*)Wh[pass] + c * 128;
        const char* wl = (const char*)Wl[pass] + c * 128;
#pragma unroll
        for (int i = 0; i < 4; i++) {
            int idx = tid + i * 256;                 // 1024: 128 rows x 8 segs
            int row = idx >> 3, seg = idx & 7;
            cpa16(st + row * ASTR + seg * 16, ah + (size_t)row * 2048 + seg * 16);
        }
#pragma unroll
        for (int i = 0; i < 4; i++) {
            int idx = tid + i * 256;
            int row = idx >> 3, seg = idx & 7;
            cpa16(st + OFF_ALO + row * ASTR + seg * 16, al + (size_t)row * 2048 + seg * 16);
        }
#pragma unroll
        for (int i = 0; i < 2; i++) {
            int idx = tid + i * 256;                 // 512: 64 rows x 8 segs
            int row = idx >> 3, seg = idx & 7;
            cpa16(st + OFF_BHI + row * ASTR + seg * 16, wh + (size_t)row * 2048 + seg * 16);
        }
#pragma unroll
        for (int i = 0; i < 2; i++) {
            int idx = tid + i * 256;
            int row = idx >> 3, seg = idx & 7;
            cpa16(st + OFF_BLO + row * ASTR + seg * 16, wl + (size_t)row * 2048 + seg * 16);
        }
        cp_commit();
    };

    const int lane = tid & 31, w = tid >> 5;
    const int mat = lane >> 3, r = lane & 7;
    // ldmatrix lane->row mappings (A: m16k16 frag; B: k16n8 frags, 2 mma per x4)
    const uint32_t a_row  = w * 16 + (mat & 1) * 8 + r;
    const uint32_t a_koff = (mat >> 1) * 8;
    const uint32_t b_roff = (mat >> 1) * 8 + r;
    const uint32_t b_koff = (mat & 1) * 8;

    float acc[8][4];
#pragma unroll
    for (int j = 0; j < 8; j++)
#pragma unroll
        for (int e = 0; e < 4; e++) acc[j][e] = 0.0f;

    load_chunk(0); load_chunk(1); load_chunk(2);

#pragma unroll 1
    for (int ch = 0; ch < C; ch++) {
        const int rem = C - 1 - ch;
        if (rem >= 2) cp_wait<2>(); else if (rem == 1) cp_wait<1>(); else cp_wait<0>();
        __syncthreads();
        const uint32_t sa = tb + (ch % 3) * STG;
#pragma unroll
        for (int ks = 0; ks < 4; ks++) {
            uint32_t ah4[4], al4[4];
            uint32_t aaddr = sa + a_row * ASTR + (ks * 16 + a_koff) * 2;
            ldm4(ah4, aaddr);
            ldm4(al4, aaddr + OFF_ALO);
#pragma unroll
            for (int q = 0; q < 4; q++) {
                uint32_t bh4[4], bl4[4];
                uint32_t baddr = sa + OFF_BHI + (q * 16 + b_roff) * ASTR + (ks * 16 + b_koff) * 2;
                ldm4(bh4, baddr);
                ldm4(bl4, baddr + (OFF_BLO - OFF_BHI));
                mma16816(acc[2 * q],     ah4, bh4[0], bh4[1]);
                mma16816(acc[2 * q + 1], ah4, bh4[2], bh4[3]);
                mma16816(acc[2 * q],     ah4, bl4[0], bl4[1]);
                mma16816(acc[2 * q + 1], ah4, bl4[2], bl4[3]);
                mma16816(acc[2 * q],     al4, bh4[0], bh4[1]);
                mma16816(acc[2 * q + 1], al4, bh4[2], bh4[3]);
            }
        }
        __syncthreads();
        if (ch + 3 < C) load_chunk(ch + 3);
    }

    // ---- epilogue: thread holds full i/f/g/o for 2 rows x 4 hid cells ----
    const int grp = lane >> 2, tig = lane & 3;
#pragma unroll
    for (int s = 0; s < 2; s++) {
        int mm = m_t * 128 + w * 16 + grp + 8 * s;
        float xv = xs ? xs[(size_t)mm * xs_stride] : 0.0f;
#pragma unroll
        for (int hp = 0; hp < 2; hp++) {
            int hid = n_t * 16 + hp * 8 + 2 * tig;
            float hn[2];
#pragma unroll
            for (int d = 0; d < 2; d++) {
                int e = 2 * s + d;
                int hd = hid + d;
                float pi = acc[0 + hp][e] + bias[hd]        + (wih ? xv * wih[hd]        : 0.f);
                float pf = acc[2 + hp][e] + bias[1024 + hd] + (wih ? xv * wih[1024 + hd] : 0.f);
                float pg = acc[4 + hp][e] + bias[2048 + hd] + (wih ? xv * wih[2048 + hd] : 0.f);
                float po = acc[6 + hp][e] + bias[3072 + hd] + (wih ? xv * wih[3072 + hd] : 0.f);
                size_t cix = (size_t)mm * Hdim + hd;
                float cn = sigmoidf_(pf) * cst[cix] + sigmoidf_(pi) * tanhf(pg);
                hn[d] = sigmoidf_(po) * tanhf(cn);
                cst[cix] = cn;
            }
            size_t hix = (size_t)mm * Hdim + hid;
            __nv_bfloat16 h0 = __float2bfloat16(hn[0]);
            __nv_bfloat16 h1 = __float2bfloat16(hn[1]);
            __nv_bfloat16 l0 = __float2bfloat16(hn[0] - __bfloat162float(h0));
            __nv_bfloat16 l1 = __float2bfloat16(hn[1] - __bfloat162float(h1));
            *(uint32_t*)&oAh[hix] = (uint32_t)__bfloat16_as_ushort(h0) | ((uint32_t)__bfloat16_as_ushort(h1) << 16);
            *(uint32_t*)&oAl[hix] = (uint32_t)__bfloat16_as_ushort(l0) | ((uint32_t)__bfloat16_as_ushort(l1) << 16);
            if (of32) *(float2*)&of32[hix] = make_float2(hn[0], hn[1]);
        }
    }
}

__device__ __forceinline__ void fc_phase(
    const float* __restrict__ h1, const float* __restrict__ fcW,
    const float* __restrict__ fcb, float* __restrict__ out, int s)
{
    if (blockIdx.x >= 32) return;
    int warp = threadIdx.x >> 5, lane = threadIdx.x & 31;
    int b = blockIdx.x * 8 + warp;
    float sum = 0.0f;
    const float* hr = h1 + (size_t)b * Hdim;
#pragma unroll 8
    for (int k = lane; k < Hdim; k += 32) sum += hr[k] * fcW[k];
#pragma unroll
    for (int o = 16; o > 0; o >>= 1) sum += __shfl_down_sync(0xFFFFFFFFu, sum, o);
    if (lane == 0) {
        float y = sum + fcb[0];
        out[(size_t)b * OUTLEN + s] = y;
        g_xt[b] = y;
    }
}

__global__ void __launch_bounds__(256, 1) lstm_mma_kernel(
    const float* __restrict__ x,
    const float* eWih0, const float* eWhh0, const float* eb0,
    const float* eWih1, const float* eWhh1, const float* eb1,
    const float* dWih0, const float* dWhh0, const float* db0,
    const float* dWih1, const float* dWhh1, const float* db1,
    const float* fcW, const float* fcb, float* __restrict__ out)
{
    extern __shared__ uint8_t dsm[];
    const uint32_t tb = smem_u32(dsm);

    const float* Ws[6] = { eWhh0, eWih1, eWhh1, dWhh0, dWih1, dWhh1 };
    prologue(Ws, x);
    grid_sync();

    int p0 = 0, p1 = 0;

#pragma unroll 1
    for (int t = 0; t < Tlen; t++) {
        lstm_phase(tb, 1,
            g_Ah[0][p0], g_Al[0][p0], g_Wh[0], g_Wl[0],
            nullptr, nullptr, nullptr, nullptr,
            eb0, eWih0, x + t, Tlen, g_c0,
            g_Ah[0][p0 ^ 1], g_Al[0][p0 ^ 1], nullptr);
        p0 ^= 1;
        grid_sync();
        lstm_phase(tb, 2,
            g_Ah[0][p0], g_Al[0][p0], g_Wh[1], g_Wl[1],
            g_Ah[1][p1], g_Al[1][p1], g_Wh[2], g_Wl[2],
            eb1, nullptr, nullptr, 0, g_c1,
            g_Ah[1][p1 ^ 1], g_Al[1][p1 ^ 1], nullptr);
        p1 ^= 1;
        grid_sync();
    }
#pragma unroll 1
    for (int s = 0; s < OUTLEN; s++) {
        lstm_phase(tb, 1,
            g_Ah[0][p0], g_Al[0][p0], g_Wh[3], g_Wl[3],
            nullptr, nullptr, nullptr, nullptr,
            db0, dWih0, g_xt, 1, g_c0,
            g_Ah[0][p0 ^ 1], g_Al[0][p0 ^ 1], nullptr);
        p0 ^= 1;
        grid_sync();
        lstm_phase(tb, 2,
            g_Ah[0][p0], g_Al[0][p0], g_Wh[4], g_Wl[4],
            g_Ah[1][p1], g_Al[1][p1], g_Wh[5], g_Wl[5],
            db1, nullptr, nullptr, 0, g_c1,
            g_Ah[1][p1 ^ 1], g_Al[1][p1 ^ 1], g_h1f);
        p1 ^= 1;
        grid_sync();
        fc_phase(g_h1f, fcW, fcb, out, s);
        grid_sync();
    }
}

extern "C" void kernel_launch(void* const* d_in, const int* in_sizes, int n_in,
                              void* d_out, int out_size)
{
    (void)in_sizes; (void)n_in; (void)out_size;
    cudaFuncSetAttribute(lstm_mma_kernel, cudaFuncAttributeMaxDynamicSharedMemorySize, SMEM_TOTAL);
    lstm_mma_kernel<<<NCTA, 256, SMEM_TOTAL>>>(
        (const float*)d_in[0],
        (const float*)d_in[1],  (const float*)d_in[2],  (const float*)d_in[3],
        (const float*)d_in[4],  (const float*)d_in[5],  (const float*)d_in[6],
        (const float*)d_in[7],  (const float*)d_in[8],  (const float*)d_in[9],
        (const float*)d_in[10], (const float*)d_in[11], (const float*)d_in[12],
        (const float*)d_in[13], (const float*)d_in[14],
        (float*)d_out);
}

// round 8
// speedup vs baseline: 4.1126x; 1.3136x over previous
#include <cuda_runtime.h>
#include <cuda_fp16.h>
#include <cstdint>
#include <cstddef>

// Persistent 2-term fp16 HMMA LSTM (portable PTX: mma.sync + ldmatrix + cp.async).
// D = Ahi*(Bhi+Blo): A (h state) stored as single fp16, W split fp16 hi/lo.
// 128 CTAs = 2 M-tiles(128 rows) x 64 N-tiles(16 hid x 4 gates).
// K=128 chunks, 3-stage cp.async pipeline, one __syncthreads per chunk.
#define Bsz 256
#define Hdim 1024
#define Tlen 336
#define OUTLEN 96
#define BH (Bsz*Hdim)
#define NCTA 128
#define ASTR 272                  // padded smem row stride for 256B rows
#define OFF_BH 34816              // A: 128 rows * 272
#define OFF_BL 52224              // + 64 rows * 272
#define STG 69632                 // + 64 rows * 272
#define SMEM_TOTAL (3*STG)        // 208896

__device__ __align__(16) __half g_Wh[6][4096 * 1024];   // gate-permuted [n_t*64+col][k]
__device__ __align__(16) __half g_Wl[6][4096 * 1024];
__device__ __align__(16) __half g_A[2][2][BH];          // h state fp16 [layer][ping][m][k]
__device__ float g_c0[BH], g_c1[BH], g_h1f[BH], g_xt[Bsz];
__device__ unsigned g_cnt, g_gen;

__device__ __forceinline__ uint32_t smem_u32(const void* p) {
    uint32_t a;
    asm("{ .reg .u64 t; cvta.to.shared.u64 t, %1; cvt.u32.u64 %0, t; }" : "=r"(a) : "l"(p));
    return a;
}
__device__ __forceinline__ void cpa16(uint32_t d, const void* s) {
    asm volatile("cp.async.cg.shared.global [%0], [%1], 16;" :: "r"(d), "l"(s));
}
__device__ __forceinline__ void cp_commit() { asm volatile("cp.async.commit_group;" ::: "memory"); }
template <int N> __device__ __forceinline__ void cp_wait() {
    asm volatile("cp.async.wait_group %0;" :: "n"(N) : "memory");
}
__device__ __forceinline__ void ldm4(uint32_t* r, uint32_t a) {
    asm volatile("ldmatrix.sync.aligned.m8n8.x4.shared.b16 {%0,%1,%2,%3}, [%4];"
        : "=r"(r[0]), "=r"(r[1]), "=r"(r[2]), "=r"(r[3]) : "r"(a));
}
__device__ __forceinline__ void mma16816(float* c, const uint32_t* a, uint32_t b0, uint32_t b1) {
    asm volatile(
        "mma.sync.aligned.m16n8k16.row.col.f32.f16.f16.f32 "
        "{%0,%1,%2,%3}, {%4,%5,%6,%7}, {%8,%9}, {%0,%1,%2,%3};"
        : "+f"(c[0]), "+f"(c[1]), "+f"(c[2]), "+f"(c[3])
        : "r"(a[0]), "r"(a[1]), "r"(a[2]), "r"(a[3]), "r"(b0), "r"(b1));
}
__device__ __forceinline__ float sigmoidf_(float x) { return 1.0f / (1.0f + expf(-x)); }

__device__ __forceinline__ void grid_sync() {
    __syncthreads();
    if (threadIdx.x == 0) {
        __threadfence();
        unsigned g = *(volatile unsigned*)&g_gen;
        unsigned a = atomicAdd(&g_cnt, 1u);
        if (a == NCTA - 1) {
            atomicExch(&g_cnt, 0u);
            __threadfence();
            atomicAdd(&g_gen, 1u);
        } else {
            while (*(volatile unsigned*)&g_gen == g) { __nanosleep(64); }
        }
        __threadfence();
    }
    __syncthreads();
}

// Split+permute 6 weight matrices into fp16 hi/lo: dst col = n_t*64 + gate*16 + hid%16.
__device__ void prologue(const float* const* Ws, const float* x) {
    const int gt = blockIdx.x * 256 + threadIdx.x;
#pragma unroll 1
    for (int mat = 0; mat < 6; mat++) {
        const float* src = Ws[mat];
#pragma unroll 1
        for (int p = gt; p < (4096 * 1024 / 2); p += NCTA * 256) {
            int gr = p >> 9;
            int k  = (p & 511) << 1;
            float2 v = *(const float2*)(src + (size_t)gr * 1024 + k);
            int gate = gr >> 10, hid = gr & 1023;
            size_t off = ((size_t)(hid >> 4) * 64 + gate * 16 + (hid & 15)) * 1024 + k;
            __half h0 = __float2half_rn(v.x);
            __half h1 = __float2half_rn(v.y);
            __half l0 = __float2half_rn(v.x - __half2float(h0));
            __half l1 = __float2half_rn(v.y - __half2float(h1));
            *(uint32_t*)&g_Wh[mat][off] = (uint32_t)__half_as_ushort(h0) | ((uint32_t)__half_as_ushort(h1) << 16);
            *(uint32_t*)&g_Wl[mat][off] = (uint32_t)__half_as_ushort(l0) | ((uint32_t)__half_as_ushort(l1) << 16);
        }
    }
    float4 zf = make_float4(0.f, 0.f, 0.f, 0.f);
    uint4 z4 = make_uint4(0, 0, 0, 0);
    for (int i = gt; i < BH / 4; i += NCTA * 256) {
        ((float4*)g_c0)[i] = zf;
        ((float4*)g_c1)[i] = zf;
    }
    for (int i = gt; i < BH / 8; i += NCTA * 256) {
        ((uint4*)g_A[0][0])[i] = z4;
        ((uint4*)g_A[1][0])[i] = z4;
    }
    if (gt < Bsz) g_xt[gt] = x[(size_t)gt * Tlen + (Tlen - 1)];
}

// One recurrence phase: D(128x64) = sum over passes Ahi@(Whi+Wlo)^T,
// fused LSTM pointwise, state write-back.
__device__ __noinline__ void lstm_phase(
    uint32_t tb, int npass,
    const __half* A0, const __half* W0h, const __half* W0l,
    const __half* A1, const __half* W1h, const __half* W1l,
    const float* __restrict__ bias, const float* __restrict__ wih,
    const float* __restrict__ xs, int xs_stride,
    float* __restrict__ cst,
    __half* __restrict__ oA, float* __restrict__ of32)
{
    const int tid = threadIdx.x;
    const int m_t = blockIdx.x & 1;
    const int n_t = blockIdx.x >> 1;
    const int C = npass << 3;               // 8 chunks of K=128 per pass

    const __half* Ap[2] = { A0 + m_t * 128 * Hdim, A1 ? A1 + m_t * 128 * Hdim : A0 };
    const __half* Wh[2] = { W0h + (size_t)n_t * 64 * Hdim, W1h ? W1h + (size_t)n_t * 64 * Hdim : W0h };
    const __half* Wl[2] = { W0l + (size_t)n_t * 64 * Hdim, W1l ? W1l + (size_t)n_t * 64 * Hdim : W0l };

    auto load_chunk = [&](int ch) {
        const int pass = ch >> 3, c = ch & 7;
        const uint32_t st = tb + (ch % 3) * STG;
        const char* a  = (const char*)Ap[pass] + c * 256;   // gmem row stride 2048B
        const char* wh = (const char*)Wh[pass] + c * 256;
        const char* wl = (const char*)Wl[pass] + c * 256;
#pragma unroll
        for (int i = 0; i < 8; i++) {               // A: 128 rows x 16 segs
            int idx = tid + i * 256;
            int row = idx >> 4, seg = idx & 15;
            cpa16(st + row * ASTR + seg * 16, a + (size_t)row * 2048 + seg * 16);
        }
#pragma unroll
        for (int i = 0; i < 4; i++) {               // Whi: 64 rows x 16 segs
            int idx = tid + i * 256;
            int row = idx >> 4, seg = idx & 15;
            cpa16(st + OFF_BH + row * ASTR + seg * 16, wh + (size_t)row * 2048 + seg * 16);
        }
#pragma unroll
        for (int i = 0; i < 4; i++) {               // Wlo
            int idx = tid + i * 256;
            int row = idx >> 4, seg = idx & 15;
            cpa16(st + OFF_BL + row * ASTR + seg * 16, wl + (size_t)row * 2048 + seg * 16);
        }
        cp_commit();
    };

    const int lane = tid & 31, w = tid >> 5;
    const int mat = lane >> 3, r = lane & 7;
    const uint32_t a_row  = w * 16 + (mat & 1) * 8 + r;
    const uint32_t a_koff = (mat >> 1) * 8;
    const uint32_t b_roff = (mat >> 1) * 8 + r;
    const uint32_t b_koff = (mat & 1) * 8;

    float acc[8][4];
#pragma unroll
    for (int j = 0; j < 8; j++)
#pragma unroll
        for (int e = 0; e < 4; e++) acc[j][e] = 0.0f;

    load_chunk(0);
    load_chunk(1);

#pragma unroll 1
    for (int ch = 0; ch < C; ch++) {
        if (ch < C - 1) cp_wait<1>(); else cp_wait<0>();
        __syncthreads();                    // smem visible + stage (ch+2)%3 free
        if (ch + 2 < C) load_chunk(ch + 2);
        const uint32_t sa = tb + (ch % 3) * STG;
#pragma unroll
        for (int ks = 0; ks < 8; ks++) {
            uint32_t a4[4];
            ldm4(a4, sa + a_row * ASTR + (ks * 16 + a_koff) * 2);
#pragma unroll
            for (int q = 0; q < 4; q++) {
                uint32_t bh4[4], bl4[4];
                uint32_t baddr = sa + OFF_BH + (q * 16 + b_roff) * ASTR + (ks * 16 + b_koff) * 2;
                ldm4(bh4, baddr);
                ldm4(bl4, baddr + (OFF_BL - OFF_BH));
                mma16816(acc[2 * q],     a4, bh4[0], bh4[1]);
                mma16816(acc[2 * q + 1], a4, bh4[2], bh4[3]);
                mma16816(acc[2 * q],     a4, bl4[0], bl4[1]);
                mma16816(acc[2 * q + 1], a4, bl4[2], bl4[3]);
            }
        }
    }

    // ---- epilogue: thread holds full i/f/g/o for 2 rows x 4 hid cells ----
    const int grp = lane >> 2, tig = lane & 3;
#pragma unroll
    for (int s = 0; s < 2; s++) {
        int mm = m_t * 128 + w * 16 + grp + 8 * s;
        float xv = xs ? xs[(size_t)mm * xs_stride] : 0.0f;
#pragma unroll
        for (int hp = 0; hp < 2; hp++) {
            int hid = n_t * 16 + hp * 8 + 2 * tig;
            float hn[2];
#pragma unroll
            for (int d = 0; d < 2; d++) {
                int e = 2 * s + d;
                int hd = hid + d;
                float pi = acc[0 + hp][e] + bias[hd]        + (wih ? xv * wih[hd]        : 0.f);
                float pf = acc[2 + hp][e] + bias[1024 + hd] + (wih ? xv * wih[1024 + hd] : 0.f);
                float pg = acc[4 + hp][e] + bias[2048 + hd] + (wih ? xv * wih[2048 + hd] : 0.f);
                float po = acc[6 + hp][e] + bias[3072 + hd] + (wih ? xv * wih[3072 + hd] : 0.f);
                size_t cix = (size_t)mm * Hdim + hd;
                float cn = sigmoidf_(pf) * cst[cix] + sigmoidf_(pi) * tanhf(pg);
                hn[d] = sigmoidf_(po) * tanhf(cn);
                cst[cix] = cn;
            }
            size_t hix = (size_t)mm * Hdim + hid;
            __half h0 = __float2half_rn(hn[0]);
            __half h1 = __float2half_rn(hn[1]);
            *(uint32_t*)&oA[hix] = (uint32_t)__half_as_ushort(h0) | ((uint32_t)__half_as_ushort(h1) << 16);
            if (of32) *(float2*)&of32[hix] = make_float2(hn[0], hn[1]);
        }
    }
}

__device__ __forceinline__ void fc_phase(
    const float* __restrict__ h1, const float* __restrict__ fcW,
    const float* __restrict__ fcb, float* __restrict__ out, int s)
{
    if (blockIdx.x >= 32) return;
    int warp = threadIdx.x >> 5, lane = threadIdx.x & 31;
    int b = blockIdx.x * 8 + warp;
    float sum = 0.0f;
    const float* hr = h1 + (size_t)b * Hdim;
#pragma unroll 8
    for (int k = lane; k < Hdim; k += 32) sum += hr[k] * fcW[k];
#pragma unroll
    for (int o = 16; o > 0; o >>= 1) sum += __shfl_down_sync(0xFFFFFFFFu, sum, o);
    if (lane == 0) {
        float y = sum + fcb[0];
        out[(size_t)b * OUTLEN + s] = y;
        g_xt[b] = y;
    }
}

__global__ void __launch_bounds__(256, 1) lstm_mma_kernel(
    const float* __restrict__ x,
    const float* eWih0, const float* eWhh0, const float* eb0,
    const float* eWih1, const float* eWhh1, const float* eb1,
    const float* dWih0, const float* dWhh0, const float* db0,
    const float* dWih1, const float* dWhh1, const float* db1,
    const float* fcW, const float* fcb, float* __restrict__ out)
{
    extern __shared__ uint8_t dsm[];
    const uint32_t tb = smem_u32(dsm);

    const float* Ws[6] = { eWhh0, eWih1, eWhh1, dWhh0, dWih1, dWhh1 };
    prologue(Ws, x);
    grid_sync();

    int p0 = 0, p1 = 0;

#pragma unroll 1
    for (int t = 0; t < Tlen; t++) {
        lstm_phase(tb, 1,
            g_A[0][p0], g_Wh[0], g_Wl[0],
            nullptr, nullptr, nullptr,
            eb0, eWih0, x + t, Tlen, g_c0,
            g_A[0][p0 ^ 1], nullptr);
        p0 ^= 1;
        grid_sync();
        lstm_phase(tb, 2,
            g_A[0][p0], g_Wh[1], g_Wl[1],
            g_A[1][p1], g_Wh[2], g_Wl[2],
            eb1, nullptr, nullptr, 0, g_c1,
            g_A[1][p1 ^ 1], nullptr);
        p1 ^= 1;
        grid_sync();
    }
#pragma unroll 1
    for (int s = 0; s < OUTLEN; s++) {
        lstm_phase(tb, 1,
            g_A[0][p0], g_Wh[3], g_Wl[3],
            nullptr, nullptr, nullptr,
            db0, dWih0, g_xt, 1, g_c0,
            g_A[0][p0 ^ 1], nullptr);
        p0 ^= 1;
        grid_sync();
        lstm_phase(tb, 2,
            g_A[0][p0], g_Wh[4], g_Wl[4],
            g_A[1][p1], g_Wh[5], g_Wl[5],
            db1, nullptr, nullptr, 0, g_c1,
            g_A[1][p1 ^ 1], g_h1f);
        p1 ^= 1;
        grid_sync();
        fc_phase(g_h1f, fcW, fcb, out, s);
        grid_sync();
    }
}

extern "C" void kernel_launch(void* const* d_in, const int* in_sizes, int n_in,
                              void* d_out, int out_size)
{
    (void)in_sizes; (void)n_in; (void)out_size;
    cudaFuncSetAttribute(lstm_mma_kernel, cudaFuncAttributeMaxDynamicSharedMemorySize, SMEM_TOTAL);
    lstm_mma_kernel<<<NCTA, 256, SMEM_TOTAL>>>(
        (const float*)d_in[0],
        (const float*)d_in[1],  (const float*)d_in[2],  (const float*)d_in[3],
        (const float*)d_in[4],  (const float*)d_in[5],  (const float*)d_in[6],
        (const float*)d_in[7],  (const float*)d_in[8],  (const float*)d_in[9],
        (const float*)d_in[10], (const float*)d_in[11], (const float*)d_in[12],
        (const float*)d_in[13], (const float*)d_in[14],
        (float*)d_out);
}

// round 9
// speedup vs baseline: 5.7065x; 1.3876x over previous
#include <cuda_runtime.h>
#include <cuda_fp16.h>
#include <cstdint>
#include <cstddef>

// Persistent 1-term fp16 HMMA LSTM (portable PTX: mma.sync + ldmatrix + cp.async).
// D = A*W, both fp16 (fp32 accum). 128 CTAs = 2 M-tiles(128) x 64 N-tiles(64 gate-cols).
// K=128 chunks, 4-stage cp.async pipeline (3-deep prefetch), 1 syncthreads/chunk.
#define Bsz 256
#define Hdim 1024
#define Tlen 336
#define OUTLEN 96
#define BH (Bsz*Hdim)
#define NCTA 128
#define ASTR 272                  // padded smem row stride for 256B rows
#define OFF_B 34816               // A: 128 rows * 272
#define STG 52224                 // + W: 64 rows * 272
#define NSTG 4
#define SMEM_TOTAL (NSTG*STG)     // 208896

__device__ __align__(16) __half g_W[6][4096 * 1024];    // gate-permuted [n_t*64+col][k]
__device__ __align__(16) __half g_A[2][2][BH];          // h state fp16 [layer][ping][m][k]
__device__ float g_c0[BH], g_c1[BH], g_h1f[BH], g_xt[Bsz];
__device__ unsigned g_cnt, g_gen;

__device__ __forceinline__ uint32_t smem_u32(const void* p) {
    uint32_t a;
    asm("{ .reg .u64 t; cvta.to.shared.u64 t, %1; cvt.u32.u64 %0, t; }" : "=r"(a) : "l"(p));
    return a;
}
__device__ __forceinline__ void cpa16(uint32_t d, const void* s) {
    asm volatile("cp.async.cg.shared.global [%0], [%1], 16;" :: "r"(d), "l"(s));
}
__device__ __forceinline__ void cp_commit() { asm volatile("cp.async.commit_group;" ::: "memory"); }
template <int N> __device__ __forceinline__ void cp_wait() {
    asm volatile("cp.async.wait_group %0;" :: "n"(N) : "memory");
}
__device__ __forceinline__ void ldm4(uint32_t* r, uint32_t a) {
    asm volatile("ldmatrix.sync.aligned.m8n8.x4.shared.b16 {%0,%1,%2,%3}, [%4];"
        : "=r"(r[0]), "=r"(r[1]), "=r"(r[2]), "=r"(r[3]) : "r"(a));
}
__device__ __forceinline__ void mma16816(float* c, const uint32_t* a, uint32_t b0, uint32_t b1) {
    asm volatile(
        "mma.sync.aligned.m16n8k16.row.col.f32.f16.f16.f32 "
        "{%0,%1,%2,%3}, {%4,%5,%6,%7}, {%8,%9}, {%0,%1,%2,%3};"
        : "+f"(c[0]), "+f"(c[1]), "+f"(c[2]), "+f"(c[3])
        : "r"(a[0]), "r"(a[1]), "r"(a[2]), "r"(a[3]), "r"(b0), "r"(b1));
}
__device__ __forceinline__ float sigmoidf_(float x) { return 1.0f / (1.0f + expf(-x)); }

__device__ __forceinline__ void grid_sync() {
    __syncthreads();
    if (threadIdx.x == 0) {
        __threadfence();
        unsigned g = *(volatile unsigned*)&g_gen;
        unsigned a = atomicAdd(&g_cnt, 1u);
        if (a == NCTA - 1) {
            atomicExch(&g_cnt, 0u);
            __threadfence();
            atomicAdd(&g_gen, 1u);
        } else {
            while (*(volatile unsigned*)&g_gen == g) { __nanosleep(64); }
        }
        __threadfence();
    }
    __syncthreads();
}

// Permute 6 weight matrices into fp16: dst col = n_t*64 + gate*16 + hid%16.
__device__ void prologue(const float* const* Ws, const float* x) {
    const int gt = blockIdx.x * 256 + threadIdx.x;
#pragma unroll 1
    for (int mat = 0; mat < 6; mat++) {
        const float* src = Ws[mat];
#pragma unroll 1
        for (int p = gt; p < (4096 * 1024 / 2); p += NCTA * 256) {
            int gr = p >> 9;
            int k  = (p & 511) << 1;
            float2 v = *(const float2*)(src + (size_t)gr * 1024 + k);
            int gate = gr >> 10, hid = gr & 1023;
            size_t off = ((size_t)(hid >> 4) * 64 + gate * 16 + (hid & 15)) * 1024 + k;
            __half h0 = __float2half_rn(v.x);
            __half h1 = __float2half_rn(v.y);
            *(uint32_t*)&g_W[mat][off] = (uint32_t)__half_as_ushort(h0) | ((uint32_t)__half_as_ushort(h1) << 16);
        }
    }
    float4 zf = make_float4(0.f, 0.f, 0.f, 0.f);
    uint4 z4 = make_uint4(0, 0, 0, 0);
    for (int i = gt; i < BH / 4; i += NCTA * 256) {
        ((float4*)g_c0)[i] = zf;
        ((float4*)g_c1)[i] = zf;
    }
    for (int i = gt; i < BH / 8; i += NCTA * 256) {
        ((uint4*)g_A[0][0])[i] = z4;
        ((uint4*)g_A[1][0])[i] = z4;
    }
    if (gt < Bsz) g_xt[gt] = x[(size_t)gt * Tlen + (Tlen - 1)];
}

// One recurrence phase: D(128x64) = sum over passes A@W^T, fused LSTM pointwise.
__device__ __noinline__ void lstm_phase(
    uint32_t tb, int npass,
    const __half* A0, const __half* W0,
    const __half* A1, const __half* W1,
    const float* __restrict__ bias, const float* __restrict__ wih,
    const float* __restrict__ xs, int xs_stride,
    float* __restrict__ cst,
    __half* __restrict__ oA, float* __restrict__ of32)
{
    const int tid = threadIdx.x;
    const int m_t = blockIdx.x & 1;
    const int n_t = blockIdx.x >> 1;
    const int C = npass << 3;               // 8 chunks of K=128 per pass

    const __half* Ap[2] = { A0 + m_t * 128 * Hdim, A1 ? A1 + m_t * 128 * Hdim : A0 };
    const __half* Wp[2] = { W0 + (size_t)n_t * 64 * Hdim, W1 ? W1 + (size_t)n_t * 64 * Hdim : W0 };

    auto load_chunk = [&](int ch) {
        const int pass = ch >> 3, c = ch & 7;
        const uint32_t st = tb + (ch % NSTG) * STG;
        const char* a = (const char*)Ap[pass] + c * 256;    // gmem row stride 2048B
        const char* w = (const char*)Wp[pass] + c * 256;
#pragma unroll
        for (int i = 0; i < 8; i++) {               // A: 128 rows x 16 segs
            int idx = tid + i * 256;
            int row = idx >> 4, seg = idx & 15;
            cpa16(st + row * ASTR + seg * 16, a + (size_t)row * 2048 + seg * 16);
        }
#pragma unroll
        for (int i = 0; i < 4; i++) {               // W: 64 rows x 16 segs
            int idx = tid + i * 256;
            int row = idx >> 4, seg = idx & 15;
            cpa16(st + OFF_B + row * ASTR + seg * 16, w + (size_t)row * 2048 + seg * 16);
        }
        cp_commit();
    };

    const int lane = tid & 31, w = tid >> 5;
    const int mat = lane >> 3, r = lane & 7;
    const uint32_t a_row  = w * 16 + (mat & 1) * 8 + r;
    const uint32_t a_koff = (mat >> 1) * 8;
    const uint32_t b_roff = (mat >> 1) * 8 + r;
    const uint32_t b_koff = (mat & 1) * 8;

    float acc[8][4];
#pragma unroll
    for (int j = 0; j < 8; j++)
#pragma unroll
        for (int e = 0; e < 4; e++) acc[j][e] = 0.0f;

    load_chunk(0);
    load_chunk(1);
    load_chunk(2);

#pragma unroll 1
    for (int ch = 0; ch < C; ch++) {
        const int rem = C - 1 - ch;
        if (rem >= 2) cp_wait<2>(); else if (rem == 1) cp_wait<1>(); else cp_wait<0>();
        __syncthreads();                    // stage ch visible; stage (ch+3)%4 free
        if (ch + 3 < C) load_chunk(ch + 3);
        const uint32_t sa = tb + (ch % NSTG) * STG;
#pragma unroll
        for (int ks = 0; ks < 8; ks++) {
            uint32_t a4[4];
            ldm4(a4, sa + a_row * ASTR + (ks * 16 + a_koff) * 2);
#pragma unroll
            for (int q = 0; q < 4; q++) {
                uint32_t b4[4];
                ldm4(b4, sa + OFF_B + (q * 16 + b_roff) * ASTR + (ks * 16 + b_koff) * 2);
                mma16816(acc[2 * q],     a4, b4[0], b4[1]);
                mma16816(acc[2 * q + 1], a4, b4[2], b4[3]);
            }
        }
    }

    // ---- epilogue: thread holds full i/f/g/o for 2 rows x 4 hid cells ----
    const int grp = lane >> 2, tig = lane & 3;
#pragma unroll
    for (int s = 0; s < 2; s++) {
        int mm = m_t * 128 + w * 16 + grp + 8 * s;
        float xv = xs ? xs[(size_t)mm * xs_stride] : 0.0f;
#pragma unroll
        for (int hp = 0; hp < 2; hp++) {
            int hid = n_t * 16 + hp * 8 + 2 * tig;
            float hn[2];
#pragma unroll
            for (int d = 0; d < 2; d++) {
                int e = 2 * s + d;
                int hd = hid + d;
                float pi = acc[0 + hp][e] + bias[hd]        + (wih ? xv * wih[hd]        : 0.f);
                float pf = acc[2 + hp][e] + bias[1024 + hd] + (wih ? xv * wih[1024 + hd] : 0.f);
                float pg = acc[4 + hp][e] + bias[2048 + hd] + (wih ? xv * wih[2048 + hd] : 0.f);
                float po = acc[6 + hp][e] + bias[3072 + hd] + (wih ? xv * wih[3072 + hd] : 0.f);
                size_t cix = (size_t)mm * Hdim + hd;
                float cn = sigmoidf_(pf) * cst[cix] + sigmoidf_(pi) * tanhf(pg);
                hn[d] = sigmoidf_(po) * tanhf(cn);
                cst[cix] = cn;
            }
            size_t hix = (size_t)mm * Hdim + hid;
            __half h0 = __float2half_rn(hn[0]);
            __half h1 = __float2half_rn(hn[1]);
            *(uint32_t*)&oA[hix] = (uint32_t)__half_as_ushort(h0) | ((uint32_t)__half_as_ushort(h1) << 16);
            if (of32) *(float2*)&of32[hix] = make_float2(hn[0], hn[1]);
        }
    }
}

__device__ __forceinline__ void fc_phase(
    const float* __restrict__ h1, const float* __restrict__ fcW,
    const float* __restrict__ fcb, float* __restrict__ out, int s)
{
    if (blockIdx.x >= 32) return;
    int warp = threadIdx.x >> 5, lane = threadIdx.x & 31;
    int b = blockIdx.x * 8 + warp;
    float sum = 0.0f;
    const float* hr = h1 + (size_t)b * Hdim;
#pragma unroll 8
    for (int k = lane; k < Hdim; k += 32) sum += hr[k] * fcW[k];
#pragma unroll
    for (int o = 16; o > 0; o >>= 1) sum += __shfl_down_sync(0xFFFFFFFFu, sum, o);
    if (lane == 0) {
        float y = sum + fcb[0];
        out[(size_t)b * OUTLEN + s] = y;
        g_xt[b] = y;
    }
}

__global__ void __launch_bounds__(256, 1) lstm_mma_kernel(
    const float* __restrict__ x,
    const float* eWih0, const float* eWhh0, const float* eb0,
    const float* eWih1, const float* eWhh1, const float* eb1,
    const float* dWih0, const float* dWhh0, const float* db0,
    const float* dWih1, const float* dWhh1, const float* db1,
    const float* fcW, const float* fcb, float* __restrict__ out)
{
    extern __shared__ uint8_t dsm[];
    const uint32_t tb = smem_u32(dsm);

    const float* Ws[6] = { eWhh0, eWih1, eWhh1, dWhh0, dWih1, dWhh1 };
    prologue(Ws, x);
    grid_sync();

    int p0 = 0, p1 = 0;

#pragma unroll 1
    for (int t = 0; t < Tlen; t++) {
        lstm_phase(tb, 1,
            g_A[0][p0], g_W[0], nullptr, nullptr,
            eb0, eWih0, x + t, Tlen, g_c0,
            g_A[0][p0 ^ 1], nullptr);
        p0 ^= 1;
        grid_sync();
        lstm_phase(tb, 2,
            g_A[0][p0], g_W[1], g_A[1][p1], g_W[2],
            eb1, nullptr, nullptr, 0, g_c1,
            g_A[1][p1 ^ 1], nullptr);
        p1 ^= 1;
        grid_sync();
    }
#pragma unroll 1
    for (int s = 0; s < OUTLEN; s++) {
        lstm_phase(tb, 1,
            g_A[0][p0], g_W[3], nullptr, nullptr,
            db0, dWih0, g_xt, 1, g_c0,
            g_A[0][p0 ^ 1], nullptr);
        p0 ^= 1;
        grid_sync();
        lstm_phase(tb, 2,
            g_A[0][p0], g_W[4], g_A[1][p1], g_W[5],
            db1, nullptr, nullptr, 0, g_c1,
            g_A[1][p1 ^ 1], g_h1f);
        p1 ^= 1;
        grid_sync();
        fc_phase(g_h1f, fcW, fcb, out, s);
        grid_sync();
    }
}

extern "C" void kernel_launch(void* const* d_in, const int* in_sizes, int n_in,
                              void* d_out, int out_size)
{
    (void)in_sizes; (void)n_in; (void)out_size;
    cudaFuncSetAttribute(lstm_mma_kernel, cudaFuncAttributeMaxDynamicSharedMemorySize, SMEM_TOTAL);
    lstm_mma_kernel<<<NCTA, 256, SMEM_TOTAL>>>(
        (const float*)d_in[0],
        (const float*)d_in[1],  (const float*)d_in[2],  (const float*)d_in[3],
        (const float*)d_in[4],  (const float*)d_in[5],  (const float*)d_in[6],
        (const float*)d_in[7],  (const float*)d_in[8],  (const float*)d_in[9],
        (const float*)d_in[10], (const float*)d_in[11], (const float*)d_in[12],
        (const float*)d_in[13], (const float*)d_in[14],
        (float*)d_out);
}